// round 5
// baseline (speedup 1.0000x reference)
#include <cuda_runtime.h>
#include <math.h>

// Problem constants (shapes fixed by setup_inputs)
#define C_DIM   20
#define C2      10          // channel pairs
#define HW      524288      // 512*1024
#define HW2     262144      // HW/2 (float2 units)
#define HW2_SH  18          // log2(HW2)
#define BLK     256

// Prep output: normalized prototypes [m][c] + per-row squared norms
__device__ float g_proto[C_DIM * C_DIM];
__device__ float g_psqn[C_DIM];

__device__ __forceinline__ float sqrt_approx(float v) {
    float r; asm("sqrt.approx.f32 %0, %1;" : "=f"(r) : "f"(v)); return r;
}
__device__ __forceinline__ float rsqrt_approx(float v) {
    float r; asm("rsqrt.approx.f32 %0, %1;" : "=f"(r) : "f"(v)); return r;
}
// packed fp32x2 FMA: d = a*b + d   (FFMA2 — only reachable via PTX)
__device__ __forceinline__ void ffma2(unsigned long long& d,
                                      unsigned long long a,
                                      unsigned long long b) {
    asm("fma.rn.f32x2 %0, %1, %2, %0;" : "+l"(d) : "l"(a), "l"(b));
}
__device__ __forceinline__ unsigned long long pack2(float lo, float hi) {
    unsigned long long r;
    asm("mov.b64 %0, {%1, %2};" : "=l"(r) : "f"(lo), "f"(hi));
    return r;
}
__device__ __forceinline__ void unpack2(float& lo, float& hi, unsigned long long v) {
    asm("mov.b64 {%0, %1}, %2;" : "=f"(lo), "=f"(hi) : "l"(v));
}

// ---------------------------------------------------------------------------
// Prep: normalize prototype rows (dim=1), store rows + squared norms.
// ---------------------------------------------------------------------------
__global__ void proto_prep_kernel(const float* __restrict__ protos) {
    int m = threadIdx.x;
    if (m < C_DIM) {
        float v[C_DIM];
        float sq = 0.f;
        #pragma unroll
        for (int c = 0; c < C_DIM; c++) {
            v[c] = protos[m * C_DIM + c];
            sq = fmaf(v[c], v[c], sq);
        }
        float inv = 1.0f / fmaxf(sqrtf(sq), 1e-12f);
        float s = 0.f;
        #pragma unroll
        for (int c = 0; c < C_DIM; c++) {
            float pv = v[c] * inv;
            g_proto[m * C_DIM + c] = pv;
            s = fmaf(pv, pv, s);
        }
        g_psqn[m] = s;
    }
}

// ---------------------------------------------------------------------------
// Main kernel: 2 consecutive pixels per thread (one float2 along W) => ~62
// regs => 4 CTAs/SM (50% occupancy). Channel-pair packing per pixel:
// xp[c2] = (x_{2c2}, x_{2c2+1}) in a 64-bit reg; dot via fma.rn.f32x2 against
// prototype channel-pairs streamed from smem as LDS.128 broadcast
// (5 per proto row).
//   input  float2 idx: b*C*HW2 + c*HW2 + rem
//   output float2 idx: b*C*HW2 + m*HW2 + rem
// ---------------------------------------------------------------------------
__global__ __launch_bounds__(BLK, 4)
void isomax_dist_kernel(const float* __restrict__ in,
                        const float* __restrict__ scale_p,
                        float* __restrict__ out) {
    __shared__ float sp[C_DIM * C_DIM];   // 80B rows = 5 x 16B, 16B-aligned
    __shared__ float spsn[C_DIM];
    for (int i = threadIdx.x; i < C_DIM * C_DIM; i += BLK)
        sp[i] = g_proto[i];
    if (threadIdx.x < C_DIM)
        spsn[threadIdx.x] = g_psqn[threadIdx.x];
    __syncthreads();

    const float sneg = -fabsf(__ldg(scale_p));   // logits = -|scale| * dist

    const float2* __restrict__ in2  = (const float2*)in;
    float2*       __restrict__ out2 = (float2*)out;

    unsigned q   = blockIdx.x * BLK + threadIdx.x;   // global pixel-pair index
    unsigned b   = q >> HW2_SH;
    unsigned rem = q & (HW2 - 1u);
    unsigned base2 = b * (C_DIM * HW2) + rem;

    // Load 20 channels for the 2 pixels (20 x LDG.64, coalesced, deep MLP);
    // pack along channel pairs per pixel and fold in the norm accumulation.
    unsigned long long xpA[C2], xpB[C2];
    unsigned long long sqA = 0ull, sqB = 0ull;
    #pragma unroll
    for (int c2 = 0; c2 < C2; c2++) {
        float2 va = in2[base2 + (unsigned)(2 * c2)     * HW2];
        float2 vb = in2[base2 + (unsigned)(2 * c2 + 1) * HW2];
        unsigned long long pa = pack2(va.x, vb.x);   // pixel A, channels (2c2, 2c2+1)
        unsigned long long pb = pack2(va.y, vb.y);   // pixel B
        xpA[c2] = pa; ffma2(sqA, pa, pa);
        xpB[c2] = pb; ffma2(sqB, pb, pb);
    }

    float loA, hiA, loB, hiB;
    unpack2(loA, hiA, sqA);
    unpack2(loB, hiB, sqB);
    float xsqA = loA + hiA, xsqB = loB + hiB;
    float invA = rsqrt_approx(fmaxf(xsqA, 1e-24f));
    float invB = rsqrt_approx(fmaxf(xsqB, 1e-24f));
    float xnA = xsqA * invA * invA;     // ||x_hat||^2
    float xnB = xsqB * invB * invB;
    float n2iA = -2.f * invA;
    float n2iB = -2.f * invB;

    #pragma unroll 1
    for (int m = 0; m < C_DIM; m++) {
        const ulonglong2* pr = (const ulonglong2*)&sp[m * C_DIM];  // 5 LDS.128
        unsigned long long accA = 0ull, accB = 0ull;
        #pragma unroll
        for (int c4 = 0; c4 < C2 / 2; c4++) {
            ulonglong2 pp = pr[c4];
            ffma2(accA, xpA[2 * c4],     pp.x);
            ffma2(accA, xpA[2 * c4 + 1], pp.y);
            ffma2(accB, xpB[2 * c4],     pp.x);
            ffma2(accB, xpB[2 * c4 + 1], pp.y);
        }
        float psn = spsn[m];

        float a0, a1, b0, b1;
        unpack2(a0, a1, accA);
        unpack2(b0, b1, accB);
        float dotA = a0 + a1;
        float dotB = b0 + b1;
        float d2A = fmaf(dotA, n2iA, xnA + psn);
        float d2B = fmaf(dotB, n2iB, xnB + psn);
        d2A = fmaxf(d2A, 0.f);
        d2B = fmaxf(d2B, 0.f);

        float2 o;
        o.x = sneg * sqrt_approx(d2A);
        o.y = sneg * sqrt_approx(d2B);
        out2[base2 + (unsigned)m * HW2] = o;
    }
}

extern "C" void kernel_launch(void* const* d_in, const int* in_sizes, int n_in,
                              void* d_out, int out_size) {
    const float* features = (const float*)d_in[0];  // [8,20,512,1024] f32
    const float* protos   = (const float*)d_in[1];  // [20,20] f32
    const float* dscale   = (const float*)d_in[2];  // [1] f32

    proto_prep_kernel<<<1, 32>>>(protos);

    int n_pix2 = (in_sizes[0] / C_DIM) / 2;         // pixel pairs
    int grid = (n_pix2 + BLK - 1) / BLK;
    isomax_dist_kernel<<<grid, BLK>>>(features, dscale, (float*)d_out);
}